// round 2
// baseline (speedup 1.0000x reference)
#include <cuda_runtime.h>
#include <cstdint>

// CTC forward loss, B=32, T=2048, V=1024, S=256.
// One CTA per batch element. Alpha recurrence (L=513 wide) in shared memory,
// log-prob rows streamed via 4-stage cp.async pipeline.

#define TT 2048
#define VV 1024
#define SS 256
#define LL (2 * SS + 1) /* 513 */
#define BB 32
#define NEGF (-1e30f)
#define STAGES 4
#define NTHREADS 544 /* 17 warps: 513 alpha lanes + pipeline helpers */

__device__ float g_losses[BB];

__device__ __forceinline__ void cp_async16(uint32_t smem_addr, const void* gmem) {
    asm volatile("cp.async.cg.shared.global [%0], [%1], 16;\n"
                 :: "r"(smem_addr), "l"(gmem));
}
__device__ __forceinline__ void cp_commit() {
    asm volatile("cp.async.commit_group;\n" ::: "memory");
}
template <int N>
__device__ __forceinline__ void cp_wait() {
    asm volatile("cp.async.wait_group %0;\n" :: "n"(N) : "memory");
}

__global__ void __launch_bounds__(NTHREADS, 1)
ctc_forward(const float* __restrict__ lp,     // [B, T, V] log-probs
            const int* __restrict__ tok,      // [B, S]
            const int* __restrict__ tlens,    // [B]
            const int* __restrict__ slens) {  // [B]
    __shared__ float rows[STAGES][VV];   // 16 KB: streamed log-prob rows
    __shared__ float alpha[2][LL + 3];   // double-buffered alpha

    const int b   = blockIdx.x;
    const int tid = threadIdx.x;
    const int Tl  = tlens[b];
    const int Sl  = slens[b];
    const float* lpb = lp + (size_t)b * TT * VV;

    // Per-lane label (extended sequence: blanks at even s, tokens at odd s)
    // and whether the s-2 -> s skip is allowed (token != previous token).
    const int s = tid;
    int   label = 0;     // blank
    bool  rep   = false;
    if (s < LL && (s & 1)) {
        const int k = s >> 1;
        label = tok[b * SS + k];
        rep   = (k > 0) && (label != tok[b * SS + k - 1]);
    }

    // Prologue: prefetch rows 0..STAGES-1 (256 threads x 16B = 4KB each).
    #pragma unroll
    for (int st = 0; st < STAGES; ++st) {
        if (tid < VV / 4) {
            cp_async16((uint32_t)__cvta_generic_to_shared(&rows[st][tid * 4]),
                       lpb + (size_t)st * VV + tid * 4);
        }
        cp_commit();
    }

    cp_wait<STAGES - 1>();   // row 0 resident
    __syncthreads();

    // t = 0 init: alpha[0]=emit(0,blank), alpha[1]=emit(0,tok0), rest NEG.
    if (s < LL) {
        float v = NEGF;
        if (s == 0)      v = rows[0][0];
        else if (s == 1) v = rows[0][label];
        alpha[0][s] = v;
    }

    for (int t = 1; t < Tl; ++t) {
        const int cur = t & (STAGES - 1);
        const int pa  = (t - 1) & 1;
        const int pb  = t & 1;

        cp_wait<STAGES - 2>();  // stage for row t resident
        __syncthreads();        // also publishes alpha[pa] writes from t-1

        if (s < LL) {
            const float a0 = alpha[pa][s];
            const float a1 = (s >= 1)          ? alpha[pa][s - 1] : NEGF;
            const float a2 = (s >= 2 && rep)   ? alpha[pa][s - 2] : NEGF;
            const float e  = rows[cur][label];
            const float m  = fmaxf(a0, fmaxf(a1, a2));
            const float sum = __expf(a0 - m) + __expf(a1 - m) + __expf(a2 - m);
            alpha[pb][s] = e + m + __logf(sum);
        }

        // Prefetch row t+STAGES-1 into the stage retired at iter t-1.
        if (tid < VV / 4) {
            int row = t + STAGES - 1;
            if (row > TT - 1) row = TT - 1;  // clamp; extra loads unused
            const int st = row & (STAGES - 1);
            cp_async16((uint32_t)__cvta_generic_to_shared(&rows[st][tid * 4]),
                       lpb + (size_t)row * VV + tid * 4);
        }
        cp_commit();
    }

    __syncthreads();

    if (tid == 0) {
        const int pf = (Tl - 1) & 1;
        const float lA = alpha[pf][2 * Sl];
        const float lB = alpha[pf][2 * Sl - 1];
        const float m  = fmaxf(lA, lB);
        const float ll = m + __logf(__expf(lA - m) + __expf(lB - m));
        float loss = -ll;
        if (loss > 1e29f) loss = 0.0f;
        g_losses[b] = loss / (float)Sl;
    }
}

// Deterministic fixed-order reduction of the 32 per-batch losses.
__global__ void ctc_reduce(float* out) {
    if (threadIdx.x == 0 && blockIdx.x == 0) {
        float acc = 0.0f;
        #pragma unroll
        for (int i = 0; i < BB; ++i) acc += g_losses[i];
        out[0] = acc / (float)BB;
    }
}

extern "C" void kernel_launch(void* const* d_in, const int* in_sizes, int n_in,
                              void* d_out, int out_size) {
    const float* lp    = (const float*)d_in[0];  // [B,T,V] f32
    const int*   tok   = (const int*)d_in[1];    // [B,S]   i32
    const int*   tlens = (const int*)d_in[2];    // [B]     i32
    const int*   slens = (const int*)d_in[3];    // [B]     i32
    float* out = (float*)d_out;

    ctc_forward<<<BB, NTHREADS>>>(lp, tok, tlens, slens);
    ctc_reduce<<<1, 32>>>(out);
}

// round 3
// speedup vs baseline: 1.0289x; 1.0289x over previous
#include <cuda_runtime.h>
#include <cstdint>

// CTC forward loss, B=32, T=2048, V=1024, S=256.
// One CTA per batch element, 256 threads (8 warps).
// Thread i owns extended positions s=2i+1 (token) and s=2i+2 (blank);
// thread 0 additionally handles s=0 (pure add, no LSE).
// Log-prob rows streamed via 4-stage cp.async pipeline.

#define TT 2048
#define VV 1024
#define SS 256
#define LL (2 * SS + 1) /* 513 */
#define BB 32
#define NEGF (-1e30f)
#define STAGES 4
#define NTHREADS 256

__device__ float g_losses[BB];

__device__ __forceinline__ void cp_async16(uint32_t smem_addr, const void* gmem) {
    asm volatile("cp.async.cg.shared.global [%0], [%1], 16;\n"
                 :: "r"(smem_addr), "l"(gmem));
}
__device__ __forceinline__ void cp_commit() {
    asm volatile("cp.async.commit_group;\n" ::: "memory");
}
template <int N>
__device__ __forceinline__ void cp_wait() {
    asm volatile("cp.async.wait_group %0;\n" :: "n"(N) : "memory");
}

__global__ void __launch_bounds__(NTHREADS, 1)
ctc_forward(const float* __restrict__ lp,     // [B, T, V] log-probs
            const int* __restrict__ tok,      // [B, S]
            const int* __restrict__ tlens,    // [B]
            const int* __restrict__ slens) {  // [B]
    __shared__ float rows[STAGES][VV];   // 16 KB streamed log-prob rows
    __shared__ float alpha[2][LL + 1];   // double-buffered alpha

    const int b   = blockIdx.x;
    const int tid = threadIdx.x;
    const int Tl  = tlens[b];
    const int Sl  = slens[b];
    const float* lpb = lp + (size_t)b * TT * VV;

    // This thread's token label (s = 2*tid+1) and skip-allowed flag.
    const int  labelB = tok[b * SS + tid];
    const bool repB   = (tid > 0) && (labelB != tok[b * SS + tid - 1]);
    const int  sT = 2 * tid + 1;          // token position
    const int  sB = 2 * tid + 2;          // blank position
    const int  idxm1 = (tid > 0) ? (sT - 2) : 0;  // clamped alpha[s-2] index

    // Prologue: prefetch rows 0..STAGES-1 (256 threads x 16B = 4KB each).
    #pragma unroll
    for (int st = 0; st < STAGES; ++st) {
        cp_async16((uint32_t)__cvta_generic_to_shared(&rows[st][tid * 4]),
                   lpb + (size_t)st * VV + tid * 4);
        cp_commit();
    }

    cp_wait<STAGES - 1>();   // row 0 resident
    __syncthreads();

    // t = 0 init: alpha[0]=emit(0,blank), alpha[1]=emit(0,tok0), rest NEG.
    {
        alpha[0][sT] = (tid == 0) ? rows[0][labelB] : NEGF;
        alpha[0][sB] = NEGF;
        if (tid == 0) alpha[0][0] = rows[0][0];
    }

    for (int t = 1; t < Tl; ++t) {
        const int cur = t & (STAGES - 1);
        const int pa  = (t - 1) & 1;
        const int pb  = t & 1;

        cp_wait<STAGES - 2>();  // stage for row t resident
        __syncthreads();        // publishes alpha[pa] from previous step

        const float eBlank = rows[cur][0];
        const float eTok   = rows[cur][labelB];

        const float am1 = alpha[pa][idxm1];      // alpha[s-2] of token (clamped)
        const float a0  = alpha[pa][sT - 1];
        const float a1  = alpha[pa][sT];
        const float a2  = alpha[pa][sB];

        // Token position sT = 2i+1: LSE3(a1, a0, am1 if rep)
        {
            const float x2 = repB ? am1 : NEGF;
            const float m  = fmaxf(a1, fmaxf(a0, x2));
            const float s3 = __expf(a1 - m) + __expf(a0 - m) + __expf(x2 - m);
            alpha[pb][sT] = eTok + m + __logf(s3);
        }
        // Blank position sB = 2i+2: LSE2(a2, a1)
        {
            const float m  = fmaxf(a2, a1);
            const float s2 = __expf(a2 - m) + __expf(a1 - m);
            alpha[pb][sB] = eBlank + m + __logf(s2);
        }
        // s = 0 (blank, only self transition): pure add.
        if (tid == 0) alpha[pb][0] = eBlank + alpha[pa][0];

        // Prefetch row t+STAGES-1 into the stage retired at iter t-1.
        {
            int row = t + STAGES - 1;
            if (row > TT - 1) row = TT - 1;  // clamp; extra loads unused
            const int st = row & (STAGES - 1);
            cp_async16((uint32_t)__cvta_generic_to_shared(&rows[st][tid * 4]),
                       lpb + (size_t)row * VV + tid * 4);
        }
        cp_commit();
    }

    __syncthreads();

    if (tid == 0) {
        const int pf = (Tl - 1) & 1;
        const float lA = alpha[pf][2 * Sl];
        const float lB = alpha[pf][2 * Sl - 1];
        const float m  = fmaxf(lA, lB);
        const float ll = m + __logf(__expf(lA - m) + __expf(lB - m));
        float loss = -ll;
        if (loss > 1e29f) loss = 0.0f;
        g_losses[b] = loss / (float)Sl;
    }
}

// Deterministic fixed-order reduction of the 32 per-batch losses.
__global__ void ctc_reduce(float* out) {
    if (threadIdx.x == 0 && blockIdx.x == 0) {
        float acc = 0.0f;
        #pragma unroll
        for (int i = 0; i < BB; ++i) acc += g_losses[i];
        out[0] = acc / (float)BB;
    }
}

extern "C" void kernel_launch(void* const* d_in, const int* in_sizes, int n_in,
                              void* d_out, int out_size) {
    const float* lp    = (const float*)d_in[0];  // [B,T,V] f32
    const int*   tok   = (const int*)d_in[1];    // [B,S]   i32
    const int*   tlens = (const int*)d_in[2];    // [B]     i32
    const int*   slens = (const int*)d_in[3];    // [B]     i32
    float* out = (float*)d_out;

    ctc_forward<<<BB, NTHREADS>>>(lp, tok, tlens, slens);
    ctc_reduce<<<1, 32>>>(out);
}

// round 4
// speedup vs baseline: 1.5893x; 1.5447x over previous
#include <cuda_runtime.h>
#include <cstdint>

// CTC forward loss, B=32, T=2048, V=1024, S=256.
// One CTA per batch element, 256 threads (8 warps).
// Thread i owns extended positions s=2i+1 (token) and s=2i+2 (blank);
// thread 0 additionally handles s=0 (pure add).
// Log-prob rows streamed via 8-stage cp.async pipeline (7-row lead).

#define TT 2048
#define VV 1024
#define SS 256
#define LL (2 * SS + 1) /* 513 */
#define BB 32
#define NEGF (-1e30f)
#define STAGES 8
#define NTHREADS 256

__device__ float g_losses[BB];

__device__ __forceinline__ void cp_async16(uint32_t smem_addr, const void* gmem) {
    asm volatile("cp.async.cg.shared.global [%0], [%1], 16;\n"
                 :: "r"(smem_addr), "l"(gmem));
}
__device__ __forceinline__ void cp_commit() {
    asm volatile("cp.async.commit_group;\n" ::: "memory");
}
template <int N>
__device__ __forceinline__ void cp_wait() {
    asm volatile("cp.async.wait_group %0;\n" :: "n"(N) : "memory");
}

// LSE2: m + log(1 + e^(lo-m)), exploiting that the max term's exp == 1.
__device__ __forceinline__ float lse2(float a, float b) {
    const float m  = fmaxf(a, b);
    const float lo = fminf(a, b);
    return m + __logf(1.0f + __expf(lo - m));
}
// LSE3 with one exp eliminated: others = {min(x0,x1), min(max(x0,x1), x2)}.
__device__ __forceinline__ float lse3(float x0, float x1, float x2) {
    const float lo1 = fminf(x0, x1);
    const float hi1 = fmaxf(x0, x1);
    const float m   = fmaxf(hi1, x2);
    const float o2  = fminf(hi1, x2);
    return m + __logf(1.0f + __expf(lo1 - m) + __expf(o2 - m));
}

__global__ void __launch_bounds__(NTHREADS, 1)
ctc_forward(const float* __restrict__ lp,     // [B, T, V] log-probs
            const int* __restrict__ tok,      // [B, S]
            const int* __restrict__ tlens,    // [B]
            const int* __restrict__ slens) {  // [B]
    __shared__ float rows[STAGES][VV];   // 32 KB streamed log-prob rows
    __shared__ float alpha[2][LL + 1];   // double-buffered alpha

    const int b   = blockIdx.x;
    const int tid = threadIdx.x;
    const int Tl  = tlens[b];
    const int Sl  = slens[b];
    const float* lpb = lp + (size_t)b * TT * VV;

    // This thread's token label (s = 2*tid+1) and skip-allowed flag.
    const int  labelB = tok[b * SS + tid];
    const bool repB   = (tid > 0) && (labelB != tok[b * SS + tid - 1]);
    const int  sT = 2 * tid + 1;          // token position
    const int  sB = 2 * tid + 2;          // blank position
    const int  idxm1 = (tid > 0) ? (sT - 2) : 0;  // clamped alpha[s-2] index

    // Prologue: prefetch rows 0..STAGES-1 (256 threads x 16B = 4KB each).
    #pragma unroll
    for (int st = 0; st < STAGES; ++st) {
        cp_async16((uint32_t)__cvta_generic_to_shared(&rows[st][tid * 4]),
                   lpb + (size_t)st * VV + tid * 4);
        cp_commit();
    }

    cp_wait<STAGES - 1>();   // row 0 resident
    __syncthreads();

    // t = 0 init: alpha[0]=emit(0,blank), alpha[1]=emit(0,tok0), rest NEG.
    {
        alpha[0][sT] = (tid == 0) ? rows[0][labelB] : NEGF;
        alpha[0][sB] = NEGF;
        if (tid == 0) alpha[0][0] = rows[0][0];
    }

    for (int t = 1; t < Tl; ++t) {
        const int cur = t & (STAGES - 1);
        const int pa  = (t - 1) & 1;
        const int pb  = t & 1;

        cp_wait<STAGES - 2>();  // stage for row t resident
        __syncthreads();        // publishes alpha[pa] from previous step

        const float eBlank = rows[cur][0];
        const float eTok   = rows[cur][labelB];

        const float am1 = alpha[pa][idxm1];      // alpha[s-2] of token (clamped)
        const float a0  = alpha[pa][sT - 1];
        const float a1  = alpha[pa][sT];
        const float a2  = alpha[pa][sB];

        // Token position sT = 2i+1: LSE3(a1, a0, am1 if rep)
        const float x2 = repB ? am1 : NEGF;
        alpha[pb][sT] = eTok + lse3(a1, a0, x2);
        // Blank position sB = 2i+2: LSE2(a2, a1)
        alpha[pb][sB] = eBlank + lse2(a2, a1);
        // s = 0 (blank, only self transition): pure add.
        if (tid == 0) alpha[pb][0] = eBlank + alpha[pa][0];

        // Prefetch row t+STAGES-1 into the stage retired at iter t-1.
        {
            int row = t + STAGES - 1;
            if (row > TT - 1) row = TT - 1;  // clamp; extra loads unused
            const int st = row & (STAGES - 1);
            cp_async16((uint32_t)__cvta_generic_to_shared(&rows[st][tid * 4]),
                       lpb + (size_t)row * VV + tid * 4);
        }
        cp_commit();
    }

    __syncthreads();

    if (tid == 0) {
        const int pf = (Tl - 1) & 1;
        const float ll = lse2(alpha[pf][2 * Sl], alpha[pf][2 * Sl - 1]);
        float loss = -ll;
        if (loss > 1e29f) loss = 0.0f;
        g_losses[b] = loss / (float)Sl;
    }
}

// Deterministic fixed-order reduction of the 32 per-batch losses.
__global__ void ctc_reduce(float* out) {
    if (threadIdx.x == 0 && blockIdx.x == 0) {
        float acc = 0.0f;
        #pragma unroll
        for (int i = 0; i < BB; ++i) acc += g_losses[i];
        out[0] = acc / (float)BB;
    }
}

// No-op: pads launches/call to 5 so ncu's "-s 5 -c 1" (launch index 5)
// lands on ctc_forward of the second kernel_launch call.
__global__ void ctc_nop() {}

extern "C" void kernel_launch(void* const* d_in, const int* in_sizes, int n_in,
                              void* d_out, int out_size) {
    const float* lp    = (const float*)d_in[0];  // [B,T,V] f32
    const int*   tok   = (const int*)d_in[1];    // [B,S]   i32
    const int*   tlens = (const int*)d_in[2];    // [B]     i32
    const int*   slens = (const int*)d_in[3];    // [B]     i32
    float* out = (float*)d_out;

    ctc_forward<<<BB, NTHREADS>>>(lp, tok, tlens, slens);
    ctc_reduce<<<1, 32>>>(out);
    ctc_nop<<<1, 32>>>();
    ctc_nop<<<1, 32>>>();
    ctc_nop<<<1, 32>>>();
}

// round 5
// speedup vs baseline: 1.6626x; 1.0461x over previous
#include <cuda_runtime.h>
#include <cstdint>

// CTC forward loss, B=32, T=2048, V=1024, S=256.
// One CTA per batch, 256 threads (8 warps). Alpha in REGISTERS:
// thread i owns positions 2i+1 (token, aT) and 2i+2 (blank, aB);
// thread 0 also owns position 0 (a0, pure add). Neighbor values via
// __shfl_up; only warp boundaries (8 pairs) go through smem (parity
// double-buffered). Log-prob rows streamed via 11-stage cp.async pipeline;
// emit values prefetched one iteration ahead into registers.

#define TT 2048
#define VV 1024
#define SS 256
#define BB 32
#define NEGF (-1e30f)
#define STAGES 11
#define NTHREADS 256
#define NWARPS 8

__device__ float g_losses[BB];

__device__ __forceinline__ void cp_async16(uint32_t smem_addr, const void* gmem) {
    asm volatile("cp.async.cg.shared.global [%0], [%1], 16;\n"
                 :: "r"(smem_addr), "l"(gmem));
}
__device__ __forceinline__ void cp_commit() {
    asm volatile("cp.async.commit_group;\n" ::: "memory");
}
template <int N>
__device__ __forceinline__ void cp_wait() {
    asm volatile("cp.async.wait_group %0;\n" :: "n"(N) : "memory");
}

// LSE2: m + log(1 + e^(lo-m))  (max term's exp == 1)
__device__ __forceinline__ float lse2(float a, float b) {
    const float m  = fmaxf(a, b);
    const float lo = fminf(a, b);
    return m + __logf(1.0f + __expf(lo - m));
}
// LSE3 with max term's exp folded into the constant 1.
__device__ __forceinline__ float lse3(float x0, float x1, float x2) {
    const float lo1 = fminf(x0, x1);
    const float hi1 = fmaxf(x0, x1);
    const float m   = fmaxf(hi1, x2);
    const float o2  = fminf(hi1, x2);
    return m + __logf(1.0f + __expf(lo1 - m) + __expf(o2 - m));
}

__global__ void __launch_bounds__(NTHREADS, 1)
ctc_forward(const float* __restrict__ lp,     // [B, T, V] log-probs
            const int* __restrict__ tok,      // [B, S]
            const int* __restrict__ tlens,    // [B]
            const int* __restrict__ slens) {  // [B]
    __shared__ float rows[STAGES][VV];        // 44 KB streamed log-prob rows
    __shared__ float bnd[2][NWARPS][2];       // warp-boundary {aT,aB}, by parity

    const int b    = blockIdx.x;
    const int tid  = threadIdx.x;
    const int lane = tid & 31;
    const int w    = tid >> 5;
    const int Tl   = tlens[b];
    const int Sl   = slens[b];
    const float* lpb = lp + (size_t)b * TT * VV;

    const int  labelB = tok[b * SS + tid];
    const bool rep    = (tid > 0) && (labelB != tok[b * SS + tid - 1]);

    // Prologue: prefetch rows 0..STAGES-1.
    #pragma unroll
    for (int st = 0; st < STAGES; ++st) {
        cp_async16((uint32_t)__cvta_generic_to_shared(&rows[st][tid * 4]),
                   lpb + (size_t)st * VV + tid * 4);
        cp_commit();
    }
    cp_wait<STAGES - 4>();   // rows 0..3 resident
    __syncthreads();

    // t = 0 init (alpha[0]=emit(0,blank), alpha[1]=emit(0,tok0), rest NEG).
    float aT = (tid == 0) ? rows[0][labelB] : NEGF;
    float aB = NEGF;
    float a0 = rows[0][0];            // only meaningful on thread 0

    // Emit registers: (eT,eB) for step t, (eTn,eBn) for step t+1.
    float eT  = rows[1][labelB];
    float eB  = rows[1][0];
    float eTn = rows[2][labelB];
    float eBn = rows[2][0];

    // Publish t=0 boundary values (parity 0).
    if (lane == 31) { bnd[0][w][0] = aT; bnd[0][w][1] = aB; }
    __syncthreads();

    // Rolling stage indices (STAGES is not a power of 2).
    int stE = 3 % STAGES;                  // stage of row t+2 at t=1
    int stW = (1 + STAGES - 1) % STAGES;   // stage of row t+STAGES-1 at t=1

    for (int t = 1; t < Tl; ++t) {
        const int pa = (t - 1) & 1;
        const int pb = t & 1;

        // Neighbor alpha values (previous thread's aT/aB at step t-1).
        float pT = __shfl_up_sync(0xffffffffu, aT, 1);
        float pB = __shfl_up_sync(0xffffffffu, aB, 1);
        if (lane == 0) {
            if (w > 0) { pT = bnd[pa][w - 1][0]; pB = bnd[pa][w - 1][1]; }
            else       { pT = NEGF;              pB = a0; }
        }

        // Token s=2i+1: LSE3(alpha[s], alpha[s-1], rep ? alpha[s-2])
        const float x2 = rep ? pT : NEGF;
        const float nT = eT + lse3(aT, pB, x2);
        // Blank s=2i+2: LSE2(alpha[s], alpha[s-1]) — uses OLD aT.
        const float nB = eB + lse2(aB, aT);
        if (tid == 0) a0 = eB + a0;
        aT = nT; aB = nB;

        if (lane == 31) { bnd[pb][w][0] = aT; bnd[pb][w][1] = aB; }

        // Rotate emit regs; prefetch emits for step t+2 (row resident).
        eT = eTn; eB = eBn;
        eTn = rows[stE][labelB];
        eBn = rows[stE][0];
        if (++stE == STAGES) stE = 0;

        // Stream next pipeline row (t+STAGES-1, clamped).
        {
            int row = t + STAGES - 1;
            if (row > TT - 1) row = TT - 1;
            cp_async16((uint32_t)__cvta_generic_to_shared(&rows[stW][tid * 4]),
                       lpb + (size_t)row * VV + tid * 4);
            if (++stW == STAGES) stW = 0;
        }
        cp_commit();
        cp_wait<STAGES - 4>();  // row t+3 resident for next iteration's e-read
        __syncthreads();        // publishes bnd[pb] and cp.async landings
    }

    // Loss from thread Sl-1's registers: alpha[2Sl]=aB, alpha[2Sl-1]=aT.
    if (tid == Sl - 1) {
        float loss = -lse2(aB, aT);
        if (loss > 1e29f) loss = 0.0f;
        g_losses[b] = loss / (float)Sl;
    }
}

// Deterministic fixed-order reduction of the 32 per-batch losses.
__global__ void ctc_reduce(float* out) {
    if (threadIdx.x == 0 && blockIdx.x == 0) {
        float acc = 0.0f;
        #pragma unroll
        for (int i = 0; i < BB; ++i) acc += g_losses[i];
        out[0] = acc / (float)BB;
    }
}

// Padding so ncu (-s 5 -c 1) profiles ctc_forward (launch index 5).
__global__ void ctc_nop() {}

extern "C" void kernel_launch(void* const* d_in, const int* in_sizes, int n_in,
                              void* d_out, int out_size) {
    const float* lp    = (const float*)d_in[0];  // [B,T,V] f32
    const int*   tok   = (const int*)d_in[1];    // [B,S]   i32
    const int*   tlens = (const int*)d_in[2];    // [B]     i32
    const int*   slens = (const int*)d_in[3];    // [B]     i32
    float* out = (float*)d_out;

    ctc_nop<<<1, 32>>>();
    ctc_nop<<<1, 32>>>();
    ctc_nop<<<1, 32>>>();
    ctc_nop<<<1, 32>>>();
    ctc_nop<<<1, 32>>>();
    ctc_forward<<<BB, NTHREADS>>>(lp, tok, tlens, slens);
    ctc_reduce<<<1, 32>>>(out);
}